// round 1
// baseline (speedup 1.0000x reference)
#include <cuda_runtime.h>
#include <stdint.h>

// Problem: out[k,l] = sum_j mitchell_mul(x[k,j], weight[l,j]) + bias[l]
// x: [512,1024] f32, weight: [512,1024] f32, bias: [512] f32, out: [512,512] f32.
//
// Mitchell approx multiply == integer add of (offset) float bit patterns:
//   bits(mitchell(|a|,|b|)) = bits(|a|) + bits(|b|) - 0x3F800000
// with sign = sign_a XOR sign_b, captured in bit 31 of the packed sum.

#define NROWS 512
#define MROWS 512
#define KDIM  1024
#define SPLITS 8
#define KC (KDIM / SPLITS)   // 128 k's per split
#define BK 32                // k's per smem stage
#define BM 128               // CTA tile rows (x rows)
#define BN 128               // CTA tile cols (w rows)
#define PADM (BM + 4)        // pad to reduce store bank conflicts, keep 16B align
#define PADN (BN + 4)

// Scratch (no allocs allowed): packed operands + split-K partials.
__device__ unsigned int g_Xp[NROWS * KDIM];
__device__ unsigned int g_Wp[MROWS * KDIM];
__device__ float        g_Part[SPLITS * NROWS * MROWS];

__device__ __forceinline__ unsigned int pack1(unsigned int b) {
    unsigned int mag = b & 0x7FFFFFFFu;
    // subtract half the bias; clamp so zeros/tiny values contribute ~2^-60 (== 0)
    unsigned int low = (mag > 0x1FC00000u) ? (mag - 0x1FC00000u) : 0u;
    return (b & 0x80000000u) | low;
}

__global__ void pack_kernel(const uint4* __restrict__ x, const uint4* __restrict__ w) {
    int i = blockIdx.x * blockDim.x + threadIdx.x;
    const int total = NROWS * KDIM / 4;
    if (i >= total) return;
    uint4 a = x[i];
    uint4 b = w[i];
    uint4 pa, pb;
    pa.x = pack1(a.x); pa.y = pack1(a.y); pa.z = pack1(a.z); pa.w = pack1(a.w);
    pb.x = pack1(b.x); pb.y = pack1(b.y); pb.z = pack1(b.z); pb.w = pack1(b.w);
    reinterpret_cast<uint4*>(g_Xp)[i] = pa;
    reinterpret_cast<uint4*>(g_Wp)[i] = pb;
}

__global__ __launch_bounds__(256, 1) void mitchell_mm_kernel() {
    __shared__ unsigned int Xs[BK][PADM];   // [k][row], transposed for LDS.128 reads
    __shared__ unsigned int Ws[BK][PADN];

    const int tid = threadIdx.x;            // 256 threads = 16x16
    const int tx = tid & 15;                // output col group
    const int ty = tid >> 4;                // output row group
    const int rowBase = blockIdx.y * BM;
    const int colBase = blockIdx.x * BN;
    const int kBase   = blockIdx.z * KC;

    float acc[8][8];
#pragma unroll
    for (int i = 0; i < 8; i++)
#pragma unroll
        for (int j = 0; j < 8; j++) acc[i][j] = 0.0f;

    for (int kk = 0; kk < BK * (KC / BK); kk += BK) {
        // Stage BK x BM (and BK x BN) tiles, transposing [row][k] -> [k][row].
        // 1024 uint4 per tile, 256 threads x 4.
#pragma unroll
        for (int v = 0; v < 4; v++) {
            int linear = tid + 256 * v;       // 0..1023
            int row = linear >> 3;            // 0..127
            int kq  = linear & 7;             // k = kq*4
            int gk  = kBase + kk + kq * 4;
            uint4 xa = *reinterpret_cast<const uint4*>(&g_Xp[(rowBase + row) * KDIM + gk]);
            Xs[kq * 4 + 0][row] = xa.x;
            Xs[kq * 4 + 1][row] = xa.y;
            Xs[kq * 4 + 2][row] = xa.z;
            Xs[kq * 4 + 3][row] = xa.w;
            uint4 wb = *reinterpret_cast<const uint4*>(&g_Wp[(colBase + row) * KDIM + gk]);
            Ws[kq * 4 + 0][row] = wb.x;
            Ws[kq * 4 + 1][row] = wb.y;
            Ws[kq * 4 + 2][row] = wb.z;
            Ws[kq * 4 + 3][row] = wb.w;
        }
        __syncthreads();

#pragma unroll 2
        for (int k = 0; k < BK; k++) {
            uint4 a0 = *reinterpret_cast<const uint4*>(&Xs[k][ty * 8]);
            uint4 a1 = *reinterpret_cast<const uint4*>(&Xs[k][ty * 8 + 4]);
            uint4 b0 = *reinterpret_cast<const uint4*>(&Ws[k][tx * 8]);
            uint4 b1 = *reinterpret_cast<const uint4*>(&Ws[k][tx * 8 + 4]);
            unsigned int a[8] = {a0.x, a0.y, a0.z, a0.w, a1.x, a1.y, a1.z, a1.w};
            unsigned int b[8] = {b0.x, b0.y, b0.z, b0.w, b1.x, b1.y, b1.z, b1.w};
#pragma unroll
            for (int i = 0; i < 8; i++)
#pragma unroll
                for (int j = 0; j < 8; j++)
                    acc[i][j] += __uint_as_float(a[i] + b[j]);
        }
        __syncthreads();
    }

    float* part = g_Part + blockIdx.z * (NROWS * MROWS);
#pragma unroll
    for (int i = 0; i < 8; i++) {
        int r = rowBase + ty * 8 + i;
        float4 s0 = make_float4(acc[i][0], acc[i][1], acc[i][2], acc[i][3]);
        float4 s1 = make_float4(acc[i][4], acc[i][5], acc[i][6], acc[i][7]);
        *reinterpret_cast<float4*>(&part[r * MROWS + colBase + tx * 8])     = s0;
        *reinterpret_cast<float4*>(&part[r * MROWS + colBase + tx * 8 + 4]) = s1;
    }
}

__global__ void reduce_kernel(const float* __restrict__ bias, float* __restrict__ out) {
    int i4 = blockIdx.x * blockDim.x + threadIdx.x;   // over N*M/4 float4s
    const int total = NROWS * MROWS / 4;
    if (i4 >= total) return;
    float4 s = reinterpret_cast<const float4*>(g_Part)[i4];
#pragma unroll
    for (int z = 1; z < SPLITS; z++) {
        float4 p = reinterpret_cast<const float4*>(g_Part + z * NROWS * MROWS)[i4];
        s.x += p.x; s.y += p.y; s.z += p.z; s.w += p.w;
    }
    int col4 = i4 & (MROWS / 4 - 1);
    float4 bv = reinterpret_cast<const float4*>(bias)[col4];
    s.x += bv.x; s.y += bv.y; s.z += bv.z; s.w += bv.w;
    reinterpret_cast<float4*>(out)[i4] = s;
}

extern "C" void kernel_launch(void* const* d_in, const int* in_sizes, int n_in,
                              void* d_out, int out_size) {
    const float* x    = (const float*)d_in[0];
    const float* w    = (const float*)d_in[1];
    const float* bias = (const float*)d_in[2];
    float* out = (float*)d_out;

    pack_kernel<<<(NROWS * KDIM / 4 + 255) / 256, 256>>>(
        (const uint4*)x, (const uint4*)w);

    dim3 grid(MROWS / BN, NROWS / BM, SPLITS);   // (4,4,8) = 128 CTAs
    mitchell_mm_kernel<<<grid, 256>>>();

    reduce_kernel<<<(NROWS * MROWS / 4 + 255) / 256, 256>>>(bias, out);
}

// round 2
// speedup vs baseline: 1.0453x; 1.0453x over previous
#include <cuda_runtime.h>
#include <stdint.h>

// out[k,l] = sum_j mitchell_mul(x[k,j], weight[l,j]) + bias[l]
// Mitchell multiply == integer add of offset float bit patterns:
//   bits(mitchell(|a|,|b|)) = bits(|a|) + bits(|b|) - 0x3F800000
// packed(v) = (sign<<31) | max(bits(|v|) - 0x1FC00000, 0); product = reinterpret(pa + pb).
// Low fields stay < 2^30 for |v| < 2^32, so no carry into the sign bit; sign adds mod-2 (XOR).

#define NROWS 512
#define MROWS 512
#define KDIM  1024
#define SPLITS 8
#define KC (KDIM / SPLITS)   // 128 k per split
#define BK 32
#define BM 128
#define BN 128
#define PADM (BM + 4)
#define PADN (BN + 4)

__device__ float g_Part[SPLITS * NROWS * MROWS];

__device__ __forceinline__ unsigned int pack1(unsigned int b) {
    unsigned int mag = b & 0x7FFFFFFFu;
    unsigned int low = (mag > 0x1FC00000u) ? (mag - 0x1FC00000u) : 0u;
    return (b & 0x80000000u) | low;
}

__global__ __launch_bounds__(256, 1) void mitchell_mm_kernel(
    const uint4* __restrict__ xq, const uint4* __restrict__ wq) {
    __shared__ unsigned int Xs[BK][PADM];   // [k][row]
    __shared__ unsigned int Ws[BK][PADN];

    const int tid = threadIdx.x;            // 256 threads = 16x16
    const int tx = tid & 15;
    const int ty = tid >> 4;
    const int rowBase = blockIdx.y * BM;
    const int colBase = blockIdx.x * BN;
    const int kBase   = blockIdx.z * KC;
    const int K4 = KDIM / 4;

    unsigned long long acc2[8][4];
#pragma unroll
    for (int i = 0; i < 8; i++)
#pragma unroll
        for (int j = 0; j < 4; j++) acc2[i][j] = 0ULL;

    // Prefetch registers for the gmem->smem pipeline (pack applied at store time).
    uint4 px[4], pw[4];
    int prow[4], pkq[4];
#pragma unroll
    for (int v = 0; v < 4; v++) {
        int lin = tid + 256 * v;            // 0..1023
        prow[v] = lin >> 3;                 // 0..127
        pkq[v]  = lin & 7;                  // k quad
    }

    auto gload = [&](int kk) {
#pragma unroll
        for (int v = 0; v < 4; v++) {
            int gk4 = (kBase + kk) / 4 + pkq[v];
            px[v] = xq[(rowBase + prow[v]) * K4 + gk4];
            pw[v] = wq[(colBase + prow[v]) * K4 + gk4];
        }
    };

    gload(0);

    for (int s = 0; s < KC / BK; s++) {
        // Store (with on-the-fly Mitchell packing) into transposed smem tiles.
#pragma unroll
        for (int v = 0; v < 4; v++) {
            int row = prow[v], kq = pkq[v];
            Xs[kq * 4 + 0][row] = pack1(px[v].x);
            Xs[kq * 4 + 1][row] = pack1(px[v].y);
            Xs[kq * 4 + 2][row] = pack1(px[v].z);
            Xs[kq * 4 + 3][row] = pack1(px[v].w);
            Ws[kq * 4 + 0][row] = pack1(pw[v].x);
            Ws[kq * 4 + 1][row] = pack1(pw[v].y);
            Ws[kq * 4 + 2][row] = pack1(pw[v].z);
            Ws[kq * 4 + 3][row] = pack1(pw[v].w);
        }
        __syncthreads();

        if (s + 1 < KC / BK) gload((s + 1) * BK);

#pragma unroll 2
        for (int k = 0; k < BK; k++) {
            uint4 a0 = *reinterpret_cast<const uint4*>(&Xs[k][ty * 8]);
            uint4 a1 = *reinterpret_cast<const uint4*>(&Xs[k][ty * 8 + 4]);
            uint4 b0 = *reinterpret_cast<const uint4*>(&Ws[k][tx * 8]);
            uint4 b1 = *reinterpret_cast<const uint4*>(&Ws[k][tx * 8 + 4]);
            unsigned int a[8] = {a0.x, a0.y, a0.z, a0.w, a1.x, a1.y, a1.z, a1.w};
            unsigned int b[8] = {b0.x, b0.y, b0.z, b0.w, b1.x, b1.y, b1.z, b1.w};
#pragma unroll
            for (int i = 0; i < 8; i++) {
#pragma unroll
                for (int j = 0; j < 4; j++) {
                    unsigned long long u;
                    asm("{\n\t"
                        ".reg .u32 lo, hi;\n\t"
                        "add.u32 lo, %1, %2;\n\t"
                        "add.u32 hi, %1, %3;\n\t"
                        "mov.b64 %0, {lo, hi};\n\t"
                        "}"
                        : "=l"(u) : "r"(a[i]), "r"(b[2 * j]), "r"(b[2 * j + 1]));
                    asm("add.rn.f32x2 %0, %0, %1;" : "+l"(acc2[i][j]) : "l"(u));
                }
            }
        }
        __syncthreads();
    }

    float* part = g_Part + blockIdx.z * (NROWS * MROWS);
#pragma unroll
    for (int i = 0; i < 8; i++) {
        int r = rowBase + ty * 8 + i;
        float res[8];
#pragma unroll
        for (int j = 0; j < 4; j++) {
            unsigned int lo, hi;
            asm("mov.b64 {%0, %1}, %2;" : "=r"(lo), "=r"(hi) : "l"(acc2[i][j]));
            res[2 * j]     = __uint_as_float(lo);
            res[2 * j + 1] = __uint_as_float(hi);
        }
        *reinterpret_cast<float4*>(&part[r * MROWS + colBase + tx * 8]) =
            make_float4(res[0], res[1], res[2], res[3]);
        *reinterpret_cast<float4*>(&part[r * MROWS + colBase + tx * 8 + 4]) =
            make_float4(res[4], res[5], res[6], res[7]);
    }
}

__global__ void reduce_kernel(const float* __restrict__ bias, float* __restrict__ out) {
    int i4 = blockIdx.x * blockDim.x + threadIdx.x;
    const int total = NROWS * MROWS / 4;
    if (i4 >= total) return;
    float4 s = reinterpret_cast<const float4*>(g_Part)[i4];
#pragma unroll
    for (int z = 1; z < SPLITS; z++) {
        float4 p = reinterpret_cast<const float4*>(g_Part + z * NROWS * MROWS)[i4];
        s.x += p.x; s.y += p.y; s.z += p.z; s.w += p.w;
    }
    int col4 = i4 & (MROWS / 4 - 1);
    float4 bv = reinterpret_cast<const float4*>(bias)[col4];
    s.x += bv.x; s.y += bv.y; s.z += bv.z; s.w += bv.w;
    reinterpret_cast<float4*>(out)[i4] = s;
}

extern "C" void kernel_launch(void* const* d_in, const int* in_sizes, int n_in,
                              void* d_out, int out_size) {
    const float* x    = (const float*)d_in[0];
    const float* w    = (const float*)d_in[1];
    const float* bias = (const float*)d_in[2];
    float* out = (float*)d_out;

    dim3 grid(MROWS / BN, NROWS / BM, SPLITS);   // (4,4,8) = 128 CTAs, one wave
    mitchell_mm_kernel<<<grid, 256>>>((const uint4*)x, (const uint4*)w);

    reduce_kernel<<<(NROWS * MROWS / 4 + 255) / 256, 256>>>(bias, out);
}

// round 3
// speedup vs baseline: 1.1565x; 1.1063x over previous
#include <cuda_runtime.h>
#include <stdint.h>

// out[k,l] = sum_j mitchell_mul(x[k,j], weight[l,j]) + bias[l]
// Mitchell multiply == integer add of offset float bit patterns:
//   packed(v) = (sign<<31) | max(bits(|v|) - 0x1FC00000, 0)
//   mitchell(a,b) = reinterpret_float(packed(a) + packed(b))
// (low fields < 2^30 for these inputs -> no carry into the sign bit; signs XOR)

#define NROWS 512
#define MROWS 512
#define KDIM  1024
#define SPLITS 8
#define KC (KDIM / SPLITS)   // 128 k per split
#define BK 32
#define BM 128               // x rows per CTA
#define BN 64                // w rows per CTA
#define PADM (BM + 4)
#define PADN (BN + 4)
#define TM 8                 // thread tile rows
#define TN 4                 // thread tile cols

__device__ float g_Part[SPLITS * NROWS * MROWS];

__device__ __forceinline__ unsigned int pack1(unsigned int b) {
    unsigned int mag = b & 0x7FFFFFFFu;
    unsigned int low = (mag > 0x1FC00000u) ? (mag - 0x1FC00000u) : 0u;
    return (b & 0x80000000u) | low;
}

__global__ __launch_bounds__(256, 2) void mitchell_mm_kernel(
    const uint4* __restrict__ xq, const uint4* __restrict__ wq) {
    __shared__ unsigned int Xs[BK][PADM];   // [k][row]
    __shared__ unsigned int Ws[BK][PADN];

    const int tid = threadIdx.x;            // 256 threads: 16 x 16
    const int tx = tid & 15;                // col group (TN=4)
    const int ty = tid >> 4;                // row group (TM=8)
    const int rowBase = blockIdx.y * BM;
    const int colBase = blockIdx.x * BN;
    const int kBase   = blockIdx.z * KC;
    const int K4 = KDIM / 4;

    float acc[TM][TN];
#pragma unroll
    for (int i = 0; i < TM; i++)
#pragma unroll
        for (int j = 0; j < TN; j++) acc[i][j] = 0.0f;

    // Staging indices: X tile 128x32 = 1024 uint4 (4 per thread),
    //                  W tile  64x32 =  512 uint4 (2 per thread).
    const int xrow = tid >> 3;              // 0..31 (+32 per v)
    const int kq   = tid & 7;               // k-quad 0..7

    uint4 px[4], pw[2];
    auto gload = [&](int kk) {
        int gk4 = (kBase + kk) / 4 + kq;
#pragma unroll
        for (int v = 0; v < 4; v++)
            px[v] = xq[(rowBase + xrow + 32 * v) * K4 + gk4];
#pragma unroll
        for (int v = 0; v < 2; v++)
            pw[v] = wq[(colBase + xrow + 32 * v) * K4 + gk4];
    };

    auto sstore = [&]() {
#pragma unroll
        for (int v = 0; v < 4; v++) {
            int r = xrow + 32 * v;
            Xs[kq * 4 + 0][r] = pack1(px[v].x);
            Xs[kq * 4 + 1][r] = pack1(px[v].y);
            Xs[kq * 4 + 2][r] = pack1(px[v].z);
            Xs[kq * 4 + 3][r] = pack1(px[v].w);
        }
#pragma unroll
        for (int v = 0; v < 2; v++) {
            int r = xrow + 32 * v;
            Ws[kq * 4 + 0][r] = pack1(pw[v].x);
            Ws[kq * 4 + 1][r] = pack1(pw[v].y);
            Ws[kq * 4 + 2][r] = pack1(pw[v].z);
            Ws[kq * 4 + 3][r] = pack1(pw[v].w);
        }
    };

    gload(0);

    for (int s = 0; s < KC / BK; s++) {
        sstore();
        __syncthreads();
        if (s + 1 < KC / BK) gload((s + 1) * BK);

#pragma unroll 4
        for (int k = 0; k < BK; k++) {
            uint4 a0 = *reinterpret_cast<const uint4*>(&Xs[k][ty * TM]);
            uint4 a1 = *reinterpret_cast<const uint4*>(&Xs[k][ty * TM + 4]);
            uint4 b0 = *reinterpret_cast<const uint4*>(&Ws[k][tx * TN]);
            unsigned int a[TM] = {a0.x, a0.y, a0.z, a0.w, a1.x, a1.y, a1.z, a1.w};
            unsigned int b[TN] = {b0.x, b0.y, b0.z, b0.w};
#pragma unroll
            for (int i = 0; i < TM; i++)
#pragma unroll
                for (int j = 0; j < TN; j++)
                    acc[i][j] += __uint_as_float(a[i] + b[j]);
        }
        __syncthreads();
    }

    float* part = g_Part + blockIdx.z * (NROWS * MROWS);
#pragma unroll
    for (int i = 0; i < TM; i++) {
        int r = rowBase + ty * TM + i;
        *reinterpret_cast<float4*>(&part[r * MROWS + colBase + tx * TN]) =
            make_float4(acc[i][0], acc[i][1], acc[i][2], acc[i][3]);
    }
}

// 128 CTAs x 256 threads, 2 float4 outputs per thread, 16 independent loads each.
__global__ __launch_bounds__(256) void reduce_kernel(
    const float* __restrict__ bias, float* __restrict__ out) {
    const int total4 = NROWS * MROWS / 4;            // 65536
    int t = blockIdx.x * blockDim.x + threadIdx.x;   // 0..32767
    int i4a = t;
    int i4b = t + total4 / 2;

    float4 sa = reinterpret_cast<const float4*>(g_Part)[i4a];
    float4 sb = reinterpret_cast<const float4*>(g_Part)[i4b];
#pragma unroll
    for (int z = 1; z < SPLITS; z++) {
        const float4* p = reinterpret_cast<const float4*>(g_Part + z * NROWS * MROWS);
        float4 pa = p[i4a];
        float4 pb = p[i4b];
        sa.x += pa.x; sa.y += pa.y; sa.z += pa.z; sa.w += pa.w;
        sb.x += pb.x; sb.y += pb.y; sb.z += pb.z; sb.w += pb.w;
    }
    float4 ba = reinterpret_cast<const float4*>(bias)[i4a & (MROWS / 4 - 1)];
    float4 bb = reinterpret_cast<const float4*>(bias)[i4b & (MROWS / 4 - 1)];
    sa.x += ba.x; sa.y += ba.y; sa.z += ba.z; sa.w += ba.w;
    sb.x += bb.x; sb.y += bb.y; sb.z += bb.z; sb.w += bb.w;
    reinterpret_cast<float4*>(out)[i4a] = sa;
    reinterpret_cast<float4*>(out)[i4b] = sb;
}

extern "C" void kernel_launch(void* const* d_in, const int* in_sizes, int n_in,
                              void* d_out, int out_size) {
    const float* x    = (const float*)d_in[0];
    const float* w    = (const float*)d_in[1];
    const float* bias = (const float*)d_in[2];
    float* out = (float*)d_out;

    dim3 grid(MROWS / BN, NROWS / BM, SPLITS);   // (8,4,8) = 256 CTAs, 2/SM
    mitchell_mm_kernel<<<grid, 256>>>((const uint4*)x, (const uint4*)w);

    reduce_kernel<<<NROWS * MROWS / 4 / 2 / 256, 256>>>(bias, out);
}